// round 6
// baseline (speedup 1.0000x reference)
#include <cuda_runtime.h>
#include <cstdint>

// ============================================================================
// LoRADense: out = x @ W + bias + (x . A[id]) . B[id]
//   x:(8192,1024)f32  ids:(8192,)i32  W:(1024,1024)f32  bias:(1024,)f32
//   lora_a:(64,1024,16)f32  lora_b:(64,16,1024)f32
//
// R6: kill LDGSTS issue bottleneck (25M cp.async.cg @8cyc ≈ 212us) with
// cp.async.bulk (sm_90 PTX, valid at plain sm_100):
//   1) prepass: x -> g_xt   tiled (32KB chunks) + SW128-swizzled + tf32 rna
//   2) prepass: W -> g_wtt  transposed, tiled (16KB chunks) + swizzled + rna
//   3) GEMM: per K-chunk stage = 2 bulk copies + mbarrier complete_tx,
//      mma.sync m16n8k8 tf32, BM=256 BN=128 BK=32, 256 thr, 64x64 warp tiles
//   4) grouped LoRA (unchanged)
// ============================================================================

#define N_TOK 8192
#define DIM   1024
#define FEAT  1024

// tiled scratch: x chunks [mt(32)][kc(32)] of 256x32 floats (32KB each)
__device__ float g_xt[N_TOK * DIM];     // 32 MB
// W^T chunks [nt(8)][kc(32)] of 128x32 floats (16KB each)
__device__ float g_wtt[FEAT * DIM];     // 4 MB

__device__ __forceinline__ uint32_t to_tf32(float v) {
    uint32_t o;
    asm("cvt.rna.tf32.f32 %0, %1;" : "=r"(o) : "f"(v));
    return o;
}
__device__ __forceinline__ uint32_t smem_u32(const void* p) {
    uint32_t a;
    asm("{ .reg .u64 t; cvta.to.shared.u64 t, %1; cvt.u32.u64 %0, t; }"
        : "=r"(a) : "l"(p));
    return a;
}
__device__ __forceinline__ void bulk_g2s(uint32_t dst, const void* src,
                                         uint32_t bytes, uint32_t mbar) {
    asm volatile(
        "cp.async.bulk.shared::cluster.global.mbarrier::complete_tx::bytes "
        "[%0], [%1], %2, [%3];"
        :: "r"(dst), "l"(src), "r"(bytes), "r"(mbar) : "memory");
}
#define MBARRIER_INIT(mbar, cnt) \
    asm volatile("mbarrier.init.shared.b64 [%0], %1;" \
                 :: "r"((uint32_t)(mbar)), "r"((uint32_t)(cnt)) : "memory")
#define MBARRIER_EXPECT_TX(mbar, bytes) \
    asm volatile("mbarrier.arrive.expect_tx.shared.b64 _, [%0], %1;" \
                 :: "r"((uint32_t)(mbar)), "r"((uint32_t)(bytes)) : "memory")
#define MBARRIER_WAIT_PARITY(mbar, parity) do {                                         \
    uint32_t _m = (uint32_t)(mbar); uint32_t _p = (uint32_t)(parity); uint32_t _d;      \
    asm volatile("{\n\t.reg .pred p;\n\t"                                               \
        "mbarrier.try_wait.parity.acquire.cta.shared::cta.b64 p, [%1], %2;\n\t"         \
        "selp.b32 %0, 1, 0, p;\n\t}"                                                    \
        : "=r"(_d) : "r"(_m), "r"(_p) : "memory");                                      \
    if (!_d) {                                                                          \
        asm volatile("{\n\t.reg .pred P1;\n\t"                                          \
            "WL_%=:\n\t"                                                                \
            "mbarrier.try_wait.parity.acquire.cta.shared::cta.b64 P1, [%0], %1, 0x989680;\n\t" \
            "@P1 bra.uni WD_%=;\n\t"                                                    \
            "bra.uni WL_%=;\n\t"                                                        \
            "WD_%=:\n\t}"                                                               \
            :: "r"(_m), "r"(_p) : "memory");                                            \
    }                                                                                   \
} while (0)

__device__ __forceinline__ void mma_tf32(float& c0, float& c1, float& c2, float& c3,
                                         uint32_t a0, uint32_t a1, uint32_t a2, uint32_t a3,
                                         uint32_t b0, uint32_t b1) {
    asm volatile(
        "mma.sync.aligned.m16n8k8.row.col.f32.tf32.tf32.f32 "
        "{%0,%1,%2,%3}, {%4,%5,%6,%7}, {%8,%9}, {%0,%1,%2,%3};"
        : "+f"(c0), "+f"(c1), "+f"(c2), "+f"(c3)
        : "r"(a0), "r"(a1), "r"(a2), "r"(a3), "r"(b0), "r"(b1));
}

// swizzled word index within a (rows x 32)-float chunk:
//   word = row*32 + (col ^ ((row&7)<<2))   (SW128, lane-constant XOR)
__device__ __forceinline__ int sw_word(int row, int col) {
    return row * 32 + (col ^ ((row & 7) << 2));
}

// ============================================================================
// Kernel 1: x -> g_xt tiled+swizzled, tf32 rna
//   grid (32 mtiles, 32 kcs), 256 thr. chunk = 256 rows x 32 cols.
// ============================================================================
__global__ void tile_x_kernel(const float* __restrict__ x) {
    const int mt = blockIdx.x, kc = blockIdx.y;
    float* dst = g_xt + (size_t)(mt * 32 + kc) * 8192;
    const float* src = x + (size_t)mt * 256 * DIM + kc * 32;
    for (int idx = threadIdx.x; idx < 8192; idx += 256) {
        int row = idx >> 5, col = idx & 31;
        float v = src[(size_t)row * DIM + col];
        dst[sw_word(row, col)] = __uint_as_float(to_tf32(v));
    }
}

// ============================================================================
// Kernel 2: W (D,F) -> g_wtt transposed+tiled+swizzled, tf32 rna
//   chunk layout: [nt(8)][kc(32)] of 128(n-rows) x 32(k-cols)
// ============================================================================
__global__ void tile_w_kernel(const float* __restrict__ W) {
    __shared__ float t[32][33];
    int fx = blockIdx.x * 32 + threadIdx.x;
    int dy = blockIdx.y * 32 + threadIdx.y;
#pragma unroll
    for (int i = 0; i < 32; i += 8)
        t[threadIdx.y + i][threadIdx.x] = W[(size_t)(dy + i) * FEAT + fx];
    __syncthreads();
    int dx = blockIdx.y * 32 + threadIdx.x;        // k index
    int kc = dx >> 5, kcol = dx & 31;
#pragma unroll
    for (int i = 0; i < 32; i += 8) {
        int fy = blockIdx.x * 32 + threadIdx.y + i;  // n index
        int nt = fy >> 7, nrow = fy & 127;
        float v = t[threadIdx.x][threadIdx.y + i];   // = W[dx][fy]
        g_wtt[(size_t)(nt * 32 + kc) * 4096 + sw_word(nrow, kcol)] =
            __uint_as_float(to_tf32(v));
    }
}

// ============================================================================
// Kernel 3: tf32 GEMM. BM=256 BN=128 BK=32. Bulk-copy pipeline, depth 3.
// ============================================================================
static constexpr int BM = 256, BN = 128, BK = 32;
static constexpr int NKCH = DIM / BK;                  // 32
static constexpr int DEPTH = 3;
static constexpr int A_WORDS = BM * BK;                // 8192 (32KB)
static constexpr int B_WORDS = BN * BK;                // 4096 (16KB)
static constexpr int STAGE_WORDS = A_WORDS + B_WORDS;  // 12288 (48KB)
static constexpr int STAGE_BYTES = STAGE_WORDS * 4;
static constexpr int MBAR_OFF = DEPTH * STAGE_BYTES;   // 147456
static constexpr int GEMM_SMEM = MBAR_OFF + 64;

__global__ void __launch_bounds__(256, 1)
gemm_tf32_kernel(const float* __restrict__ bias, float* __restrict__ out) {
    extern __shared__ float smem[];
    uint32_t sb = smem_u32(smem);
    uint32_t mb = sb + MBAR_OFF;

    const int tid = threadIdx.x;
    const int wid = tid >> 5, lane = tid & 31;
    const int wm = wid >> 1, wn = wid & 1;          // 4x2 warps, 64x64 tiles
    const int qr = lane >> 2, qc = lane & 3;
    const int xq = qr << 2;                          // swizzle XOR (lane const)
    const int bx = blockIdx.x, by = blockIdx.y;

    if (tid < DEPTH) MBARRIER_INIT(mb + tid * 8, 1);
    __syncthreads();

    const float* Abase = g_xt  + (size_t)bx * NKCH * A_WORDS;
    const float* Bbase = g_wtt + (size_t)by * NKCH * B_WORDS;

    // issue stage for chunk kc into slot
    auto issue = [&](int kc, int slot) {
        uint32_t bar = mb + slot * 8;
        uint32_t dst = sb + slot * STAGE_BYTES;
        MBARRIER_EXPECT_TX(bar, (uint32_t)STAGE_BYTES);
        bulk_g2s(dst,                 Abase + (size_t)kc * A_WORDS, A_WORDS * 4, bar);
        bulk_g2s(dst + A_WORDS * 4u,  Bbase + (size_t)kc * B_WORDS, B_WORDS * 4, bar);
    };

    if (tid == 0) { issue(0, 0); issue(1, 1); }

    float acc[4][8][4];
#pragma unroll
    for (int mi = 0; mi < 4; mi++)
#pragma unroll
        for (int ni = 0; ni < 8; ni++)
#pragma unroll
            for (int q = 0; q < 4; q++) acc[mi][ni][q] = 0.f;

#pragma unroll 1
    for (int i = 0; i < NKCH; i++) {
        const int slot = i % DEPTH;
        MBARRIER_WAIT_PARITY(mb + slot * 8, (i / DEPTH) & 1);
        __syncthreads();   // all warps finished chunk i-1 -> its slot reusable

        if (i + 2 < NKCH && tid == 0) issue(i + 2, (i + 2) % DEPTH);

        const uint32_t* As = (const uint32_t*)(smem + slot * STAGE_WORDS);
        const uint32_t* Bs = As + A_WORDS;

#pragma unroll
        for (int ks = 0; ks < 4; ks++) {
            const int kb = ks * 8;
            const int c0 = (kb + qc) ^ xq;
            const int c1 = (kb + qc + 4) ^ xq;
            uint32_t a[4][4];
#pragma unroll
            for (int mi = 0; mi < 4; mi++) {
                int row = wm * 64 + mi * 16 + qr;
                a[mi][0] = As[row * 32 + c0];
                a[mi][1] = As[(row + 8) * 32 + c0];
                a[mi][2] = As[row * 32 + c1];
                a[mi][3] = As[(row + 8) * 32 + c1];
            }
            uint32_t b[8][2];
#pragma unroll
            for (int ni = 0; ni < 8; ni++) {
                int col = wn * 64 + ni * 8 + qr;
                b[ni][0] = Bs[col * 32 + c0];
                b[ni][1] = Bs[col * 32 + c1];
            }
#pragma unroll
            for (int mi = 0; mi < 4; mi++)
#pragma unroll
                for (int ni = 0; ni < 8; ni++)
                    mma_tf32(acc[mi][ni][0], acc[mi][ni][1],
                             acc[mi][ni][2], acc[mi][ni][3],
                             a[mi][0], a[mi][1], a[mi][2], a[mi][3],
                             b[ni][0], b[ni][1]);
        }
    }

    // epilogue: out = acc + bias
#pragma unroll
    for (int mi = 0; mi < 4; mi++) {
        int row0 = bx * BM + wm * 64 + mi * 16 + qr;
#pragma unroll
        for (int ni = 0; ni < 8; ni++) {
            int col = by * BN + wn * 64 + ni * 8 + 2 * qc;
            float bxv = bias[col], byv = bias[col + 1];
            float2 v0 = make_float2(acc[mi][ni][0] + bxv, acc[mi][ni][1] + byv);
            float2 v1 = make_float2(acc[mi][ni][2] + bxv, acc[mi][ni][3] + byv);
            *(float2*)(out + (size_t)row0 * FEAT + col)       = v0;
            *(float2*)(out + (size_t)(row0 + 8) * FEAT + col) = v1;
        }
    }
}

// ============================================================================
// Kernel 4: grouped LoRA. 2 CTAs per adapter (token-parity split).
// ============================================================================
static constexpr int APAD = 17;
static constexpr int LORA_A_FLOATS = DIM * APAD;   // 17408
static constexpr int LORA_SMEM =
    LORA_A_FLOATS * 4 + 16 * FEAT * 4 + 1024 * 4 + 8 * 16 * 4 + 64;

__global__ void __launch_bounds__(256, 1)
lora_kernel(const float* __restrict__ x, const int* __restrict__ ids,
            const float* __restrict__ lora_a, const float* __restrict__ lora_b,
            float* __restrict__ out) {
    extern __shared__ char dsm[];
    float* A_s  = (float*)dsm;                     // [DIM][APAD]
    float* B_s  = A_s + LORA_A_FLOATS;             // [16][FEAT]
    int*   list = (int*)(B_s + 16 * FEAT);         // [1024]
    float* rv_s = (float*)(list + 1024);           // [8][16]
    int*   cnt  = (int*)(rv_s + 8 * 16);

    const int tid  = threadIdx.x;
    const int warp = tid >> 5, lane = tid & 31;
    const int slot = blockIdx.x >> 1;
    const int sub  = blockIdx.x & 1;

    if (tid == 0) *cnt = 0;

    {   // load A[slot] (1024x16) into padded SMEM
        const float4* ap = (const float4*)(lora_a + (size_t)slot * DIM * 16);
        for (int i = tid; i < DIM * 16 / 4; i += 256) {
            float4 v = ap[i];
            int d = i >> 2, r = (i & 3) * 4;
            float* drow = &A_s[d * APAD + r];
            drow[0] = v.x; drow[1] = v.y; drow[2] = v.z; drow[3] = v.w;
        }
    }
    {   // load B[slot] (16x1024)
        const float4* bp = (const float4*)(lora_b + (size_t)slot * 16 * FEAT);
        float4* bs = (float4*)B_s;
        for (int i = tid; i < 16 * FEAT / 4; i += 256) bs[i] = bp[i];
    }
    __syncthreads();

    for (int m = tid; m < N_TOK / 2; m += 256) {
        int n = sub + 2 * m;
        if (ids[n] == slot) {
            int p = atomicAdd(cnt, 1);
            if (p < 1024) list[p] = n;
        }
    }
    __syncthreads();
    int total = min(*cnt, 1024);

    for (int i = warp; i < total; i += 8) {
        int n = list[i];
        const float* xr = x + (size_t)n * DIM;

        float accr[16];
#pragma unroll
        for (int r = 0; r < 16; r++) accr[r] = 0.f;
        for (int kk = 0; kk < 32; kk++) {
            int d = kk * 32 + lane;
            float xv = xr[d];
            const float* ar = &A_s[d * APAD];
#pragma unroll
            for (int r = 0; r < 16; r++) accr[r] = fmaf(xv, ar[r], accr[r]);
        }
#pragma unroll
        for (int r = 0; r < 16; r++) {
            float v = accr[r];
#pragma unroll
            for (int o = 16; o > 0; o >>= 1) v += __shfl_xor_sync(0xFFFFFFFFu, v, o);
            if (lane == 0) rv_s[warp * 16 + r] = v;
        }
        __syncwarp();
        float rv[16];
#pragma unroll
        for (int r = 0; r < 16; r++) rv[r] = rv_s[warp * 16 + r];
        __syncwarp();

        float* orow = out + (size_t)n * FEAT;
        for (int kk = 0; kk < 32; kk++) {
            int f = kk * 32 + lane;
            float a = 0.f;
#pragma unroll
            for (int r = 0; r < 16; r++) a = fmaf(rv[r], B_s[r * FEAT + f], a);
            orow[f] += a;
        }
    }
}

// ============================================================================
// Launch
// ============================================================================
extern "C" void kernel_launch(void* const* d_in, const int* in_sizes, int n_in,
                              void* d_out, int out_size) {
    const float* x      = (const float*)d_in[0];
    const int*   ids    = (const int*)d_in[1];
    const float* W      = (const float*)d_in[2];
    const float* bias   = (const float*)d_in[3];
    const float* lora_a = (const float*)d_in[4];
    const float* lora_b = (const float*)d_in[5];
    float* out = (float*)d_out;

    cudaFuncSetAttribute(gemm_tf32_kernel,
                         cudaFuncAttributeMaxDynamicSharedMemorySize, GEMM_SMEM);
    cudaFuncSetAttribute(lora_kernel,
                         cudaFuncAttributeMaxDynamicSharedMemorySize, LORA_SMEM);

    tile_x_kernel<<<dim3(32, 32), 256>>>(x);
    tile_w_kernel<<<dim3(FEAT / 32, DIM / 32), dim3(32, 8)>>>(W);

    dim3 ggrid(N_TOK / BM, FEAT / BN);   // 32 x 8
    gemm_tf32_kernel<<<ggrid, 256, GEMM_SMEM>>>(bias, out);

    lora_kernel<<<128, 256, LORA_SMEM>>>(x, ids, lora_a, lora_b, out);
}

// round 7
// speedup vs baseline: 1.3974x; 1.3974x over previous
#include <cuda_runtime.h>
#include <cstdint>

// ============================================================================
// LoRADense: out = x @ W + bias + (x . A[id]) . B[id]
//   x:(8192,1024)f32  ids:(8192,)i32  W:(1024,1024)f32  bias:(1024,)f32
//   lora_a:(64,1024,16)f32  lora_b:(64,16,1024)f32
//
// R7: GEMM back to R5 cp.async design (~65us measured); LoRA rewritten:
//   - 2 tokens per warp (A_s/B_s smem reads amortized over both)
//   - x rows staged in registers (MLP=32+ coalesced LDG)
//   - APAD=20 -> conflict-free LDS.128 on A_s
//   - butterfly all-reduce for rv (no smem round trip)
//   - float4 RMW on out
// ============================================================================

#define N_TOK 8192
#define DIM   1024
#define FEAT  1024

__device__ float g_wt[FEAT * DIM];   // W^T, tf32-rounded (4 MB scratch)

__device__ __forceinline__ uint32_t to_tf32(float v) {
    uint32_t o;
    asm("cvt.rna.tf32.f32 %0, %1;" : "=r"(o) : "f"(v));
    return o;
}
__device__ __forceinline__ void cp16(uint32_t dst, const void* src) {
    asm volatile("cp.async.cg.shared.global [%0], [%1], 16;" :: "r"(dst), "l"(src));
}
__device__ __forceinline__ uint32_t smem_u32(const void* p) {
    uint32_t a;
    asm("{ .reg .u64 t; cvta.to.shared.u64 t, %1; cvt.u32.u64 %0, t; }"
        : "=r"(a) : "l"(p));
    return a;
}
__device__ __forceinline__ void mma_tf32(float& c0, float& c1, float& c2, float& c3,
                                         uint32_t a0, uint32_t a1, uint32_t a2, uint32_t a3,
                                         uint32_t b0, uint32_t b1) {
    asm volatile(
        "mma.sync.aligned.m16n8k8.row.col.f32.tf32.tf32.f32 "
        "{%0,%1,%2,%3}, {%4,%5,%6,%7}, {%8,%9}, {%0,%1,%2,%3};"
        : "+f"(c0), "+f"(c1), "+f"(c2), "+f"(c3)
        : "r"(a0), "r"(a1), "r"(a2), "r"(a3), "r"(b0), "r"(b1));
}

// ============================================================================
// Kernel 1: W (D,F) -> g_wt (F,D), tf32-rounded
// ============================================================================
__global__ void transpose_w_kernel(const float* __restrict__ W) {
    __shared__ float t[32][33];
    int fx = blockIdx.x * 32 + threadIdx.x;
    int dy = blockIdx.y * 32 + threadIdx.y;
#pragma unroll
    for (int i = 0; i < 32; i += 8)
        t[threadIdx.y + i][threadIdx.x] = W[(size_t)(dy + i) * FEAT + fx];
    __syncthreads();
    int dx = blockIdx.y * 32 + threadIdx.x;
    int fy = blockIdx.x * 32 + threadIdx.y;
#pragma unroll
    for (int i = 0; i < 32; i += 8)
        g_wt[(size_t)(fy + i) * DIM + dx] =
            __uint_as_float(to_tf32(t[threadIdx.x][threadIdx.y + i]));
}

// ============================================================================
// Kernel 2: tf32 GEMM (R5 design), BM=256 BN=128 BK=32, 256 thr, 64x64 tiles
// ============================================================================
static constexpr int BM = 256, BN = 128, BK = 32;
static constexpr int AS = 36;
static constexpr int NKCH = DIM / BK;
static constexpr int DEPTH = 3;
static constexpr int A_FLOATS = BM * AS;
static constexpr int B_FLOATS = BN * AS;
static constexpr int STAGE_FLOATS = A_FLOATS + B_FLOATS;
static constexpr int GEMM_SMEM = DEPTH * STAGE_FLOATS * 4;   // 165888 B

__device__ __forceinline__ void load_stage(uint32_t sb, int slot, int kc,
                                           const float* __restrict__ x,
                                           int mbase, int nbase, int tid) {
    uint32_t baseA = sb + (uint32_t)(slot * STAGE_FLOATS) * 4u;
    uint32_t baseB = baseA + (uint32_t)A_FLOATS * 4u;
    const float* xp = x    + (size_t)mbase * DIM + kc * BK;
    const float* wp = g_wt + (size_t)nbase * DIM + kc * BK;
#pragma unroll
    for (int it = 0; it < 8; it++) {
        int c  = tid + it * 256;
        int r  = c >> 3, cc = c & 7;
        cp16(baseA + (uint32_t)(r * AS + cc * 4) * 4u, xp + (size_t)r * DIM + cc * 4);
    }
#pragma unroll
    for (int it = 0; it < 4; it++) {
        int c  = tid + it * 256;
        int r  = c >> 3, cc = c & 7;
        cp16(baseB + (uint32_t)(r * AS + cc * 4) * 4u, wp + (size_t)r * DIM + cc * 4);
    }
}

__global__ void __launch_bounds__(256, 1)
gemm_tf32_kernel(const float* __restrict__ x, const float* __restrict__ bias,
                 float* __restrict__ out) {
    extern __shared__ float smem[];
    uint32_t sb = smem_u32(smem);

    const int tid = threadIdx.x;
    const int wid = tid >> 5, lane = tid & 31;
    const int wm = wid >> 1, wn = wid & 1;
    const int qr = lane >> 2, qc = lane & 3;
    const int mbase = blockIdx.x * BM;
    const int nbase = blockIdx.y * BN;

    float acc[4][8][4];
#pragma unroll
    for (int mi = 0; mi < 4; mi++)
#pragma unroll
        for (int ni = 0; ni < 8; ni++)
#pragma unroll
            for (int q = 0; q < 4; q++) acc[mi][ni][q] = 0.f;

    load_stage(sb, 0, 0, x, mbase, nbase, tid);
    asm volatile("cp.async.commit_group;" ::: "memory");
    load_stage(sb, 1, 1, x, mbase, nbase, tid);
    asm volatile("cp.async.commit_group;" ::: "memory");

#pragma unroll 1
    for (int i = 0; i < NKCH; i++) {
        if (i >= NKCH - 1) asm volatile("cp.async.wait_group 0;" ::: "memory");
        else               asm volatile("cp.async.wait_group 1;" ::: "memory");
        __syncthreads();

        if (i + 2 < NKCH) {
            load_stage(sb, (i + 2) % DEPTH, i + 2, x, mbase, nbase, tid);
            asm volatile("cp.async.commit_group;" ::: "memory");
        }

        const int slot = i % DEPTH;
        const uint32_t* As = (const uint32_t*)(smem + slot * STAGE_FLOATS);
        const uint32_t* Bs = As + A_FLOATS;

#pragma unroll
        for (int ks = 0; ks < 4; ks++) {
            const int kb = ks * 8;
            uint32_t a[4][4];
#pragma unroll
            for (int mi = 0; mi < 4; mi++) {
                int row = wm * 64 + mi * 16 + qr;
                a[mi][0] = As[row * AS + kb + qc];
                a[mi][1] = As[(row + 8) * AS + kb + qc];
                a[mi][2] = As[row * AS + kb + qc + 4];
                a[mi][3] = As[(row + 8) * AS + kb + qc + 4];
            }
            uint32_t b[8][2];
#pragma unroll
            for (int ni = 0; ni < 8; ni++) {
                int col = wn * 64 + ni * 8 + qr;
                b[ni][0] = Bs[col * AS + kb + qc];
                b[ni][1] = Bs[col * AS + kb + qc + 4];
            }
#pragma unroll
            for (int mi = 0; mi < 4; mi++)
#pragma unroll
                for (int ni = 0; ni < 8; ni++)
                    mma_tf32(acc[mi][ni][0], acc[mi][ni][1],
                             acc[mi][ni][2], acc[mi][ni][3],
                             a[mi][0], a[mi][1], a[mi][2], a[mi][3],
                             b[ni][0], b[ni][1]);
        }
    }

#pragma unroll
    for (int mi = 0; mi < 4; mi++) {
        int row0 = mbase + wm * 64 + mi * 16 + qr;
#pragma unroll
        for (int ni = 0; ni < 8; ni++) {
            int col = nbase + wn * 64 + ni * 8 + 2 * qc;
            float bx = bias[col], by = bias[col + 1];
            float2 v0 = make_float2(acc[mi][ni][0] + bx, acc[mi][ni][1] + by);
            float2 v1 = make_float2(acc[mi][ni][2] + bx, acc[mi][ni][3] + by);
            *(float2*)(out + (size_t)row0 * FEAT + col)       = v0;
            *(float2*)(out + (size_t)(row0 + 8) * FEAT + col) = v1;
        }
    }
}

// ============================================================================
// Kernel 3: grouped LoRA, 2 CTAs/adapter, 2 tokens/warp, reg-staged x,
//           LDS.128 A/B reads, float4 RMW of out.
// ============================================================================
static constexpr int APAD = 20;                    // float4-aligned, cf-free
static constexpr int LORA_A_FLOATS = DIM * APAD;   // 20480 (80KB)
static constexpr int LORA_SMEM =
    LORA_A_FLOATS * 4 + 16 * FEAT * 4 + 1024 * 4 + 64;   // ~151.7 KB

__global__ void __launch_bounds__(256, 1)
lora_kernel(const float* __restrict__ x, const int* __restrict__ ids,
            const float* __restrict__ lora_a, const float* __restrict__ lora_b,
            float* __restrict__ out) {
    extern __shared__ char dsm[];
    float* A_s  = (float*)dsm;                     // [DIM][APAD]
    float* B_s  = A_s + LORA_A_FLOATS;             // [16][FEAT]
    int*   list = (int*)(B_s + 16 * FEAT);         // [1024]
    int*   cnt  = list + 1024;

    const int tid  = threadIdx.x;
    const int warp = tid >> 5, lane = tid & 31;
    const int slot = blockIdx.x >> 1;
    const int sub  = blockIdx.x & 1;

    if (tid == 0) *cnt = 0;

    {   // A[slot] (1024x16) -> A_s rows of APAD (float4 stores, pad stays junk)
        const float4* ap = (const float4*)(lora_a + (size_t)slot * DIM * 16);
        float4* as4 = (float4*)A_s;
        for (int i = tid; i < DIM * 4; i += 256) {     // 1024 rows x 4 quads
            int d = i >> 2, q = i & 3;
            as4[d * 5 + q] = ap[i];
        }
    }
    {   // B[slot] (16x1024) -> B_s
        const float4* bp = (const float4*)(lora_b + (size_t)slot * 16 * FEAT);
        float4* bs = (float4*)B_s;
        for (int i = tid; i < 16 * FEAT / 4; i += 256) bs[i] = bp[i];
    }
    __syncthreads();

    for (int m = tid; m < N_TOK / 2; m += 256) {
        int n = sub + 2 * m;
        if (ids[n] == slot) {
            int p = atomicAdd(cnt, 1);
            if (p < 1024) list[p] = n;
        }
    }
    __syncthreads();
    const int total = min(*cnt, 1024);

    for (int i = warp * 2; i < total; i += 16) {
        const int n0 = list[i];
        const bool has1 = (i + 1 < total);
        const int n1 = has1 ? list[i + 1] : n0;
        const float* x0 = x + (size_t)n0 * DIM;
        const float* x1 = x + (size_t)n1 * DIM;

        // stage x rows in registers: d = k*32 + lane (coalesced 128B lines)
        float xv0[32], xv1[32];
#pragma unroll
        for (int k = 0; k < 32; k++) {
            xv0[k] = x0[k * 32 + lane];
            xv1[k] = x1[k * 32 + lane];
        }

        // phase 1: partial rv over this lane's d values (LDS.128 on A_s)
        float a0[16], a1[16];
#pragma unroll
        for (int r = 0; r < 16; r++) { a0[r] = 0.f; a1[r] = 0.f; }
#pragma unroll
        for (int k = 0; k < 32; k++) {
            const float4* ar = (const float4*)&A_s[(k * 32 + lane) * APAD];
#pragma unroll
            for (int q = 0; q < 4; q++) {
                float4 av = ar[q];
                a0[q*4+0] = fmaf(xv0[k], av.x, a0[q*4+0]);
                a0[q*4+1] = fmaf(xv0[k], av.y, a0[q*4+1]);
                a0[q*4+2] = fmaf(xv0[k], av.z, a0[q*4+2]);
                a0[q*4+3] = fmaf(xv0[k], av.w, a0[q*4+3]);
                a1[q*4+0] = fmaf(xv1[k], av.x, a1[q*4+0]);
                a1[q*4+1] = fmaf(xv1[k], av.y, a1[q*4+1]);
                a1[q*4+2] = fmaf(xv1[k], av.z, a1[q*4+2]);
                a1[q*4+3] = fmaf(xv1[k], av.w, a1[q*4+3]);
            }
        }
        // butterfly all-reduce: every lane ends with the full rv
#pragma unroll
        for (int r = 0; r < 16; r++) {
#pragma unroll
            for (int o = 16; o > 0; o >>= 1) {
                a0[r] += __shfl_xor_sync(0xFFFFFFFFu, a0[r], o);
                a1[r] += __shfl_xor_sync(0xFFFFFFFFu, a1[r], o);
            }
        }

        // phase 2: out[n,f] += rv . B  (float4 lanes, B_s shared across pair)
        float4* o0 = (float4*)(out + (size_t)n0 * FEAT);
        float4* o1 = (float4*)(out + (size_t)n1 * FEAT);
        const float4* B4 = (const float4*)B_s;
#pragma unroll
        for (int j = 0; j < 8; j++) {
            int f4 = j * 32 + lane;
            float4 v0 = o0[f4];
            float4 v1 = has1 ? o1[f4] : v0;
#pragma unroll
            for (int r = 0; r < 16; r++) {
                float4 b = B4[r * 256 + f4];
                v0.x = fmaf(a0[r], b.x, v0.x); v0.y = fmaf(a0[r], b.y, v0.y);
                v0.z = fmaf(a0[r], b.z, v0.z); v0.w = fmaf(a0[r], b.w, v0.w);
                v1.x = fmaf(a1[r], b.x, v1.x); v1.y = fmaf(a1[r], b.y, v1.y);
                v1.z = fmaf(a1[r], b.z, v1.z); v1.w = fmaf(a1[r], b.w, v1.w);
            }
            o0[f4] = v0;
            if (has1) o1[f4] = v1;
        }
    }
}

// ============================================================================
// Launch
// ============================================================================
extern "C" void kernel_launch(void* const* d_in, const int* in_sizes, int n_in,
                              void* d_out, int out_size) {
    const float* x      = (const float*)d_in[0];
    const int*   ids    = (const int*)d_in[1];
    const float* W      = (const float*)d_in[2];
    const float* bias   = (const float*)d_in[3];
    const float* lora_a = (const float*)d_in[4];
    const float* lora_b = (const float*)d_in[5];
    float* out = (float*)d_out;

    cudaFuncSetAttribute(gemm_tf32_kernel,
                         cudaFuncAttributeMaxDynamicSharedMemorySize, GEMM_SMEM);
    cudaFuncSetAttribute(lora_kernel,
                         cudaFuncAttributeMaxDynamicSharedMemorySize, LORA_SMEM);

    dim3 tgrid(FEAT / 32, DIM / 32);
    transpose_w_kernel<<<tgrid, dim3(32, 8)>>>(W);

    dim3 ggrid(N_TOK / BM, FEAT / BN);   // 32 x 8
    gemm_tf32_kernel<<<ggrid, 256, GEMM_SMEM>>>(x, bias, out);

    lora_kernel<<<128, 256, LORA_SMEM>>>(x, ids, lora_a, lora_b, out);
}